// round 2
// baseline (speedup 1.0000x reference)
#include <cuda_runtime.h>

#define NL 7
#define BATCH 524288

// Output layout (reference returns (ts, quats)):
//   ts:    [NL, BATCH, 3]  floats at out[0 ..)
//   quats: [NL, BATCH, 4]  floats at out[NL*BATCH*3 ..)

__global__ __launch_bounds__(256)
void fk_kernel(const float* __restrict__ q,
               const float* __restrict__ rot_fixed,
               const float* __restrict__ trans_fixed,
               float* __restrict__ out)
{
    __shared__ float sR[NL * 9];
    __shared__ float sT[NL * 3];
    {
        int tid = threadIdx.x;
        if (tid < NL * 9) sR[tid] = rot_fixed[tid];
        if (tid < NL * 3) sT[tid] = trans_fixed[tid];
    }
    __syncthreads();

    int b = blockIdx.x * blockDim.x + threadIdx.x;
    if (b >= BATCH) return;

    // Load joint angles (7 consecutive floats per pose)
    float qv[NL];
    #pragma unroll
    for (int i = 0; i < NL; i++) qv[i] = __ldg(&q[b * NL + i]);

    // World pose (starts at identity / zero)
    float R0 = 1.f, R1 = 0.f, R2 = 0.f;
    float R3 = 0.f, R4 = 1.f, R5 = 0.f;
    float R6 = 0.f, R7 = 0.f, R8 = 1.f;
    float t0 = 0.f, t1 = 0.f, t2 = 0.f;

    float*  ts_out = out;                          // [NL, BATCH, 3]
    float4* qu_out = (float4*)(out + (size_t)NL * BATCH * 3); // [NL, BATCH, 4]

    #pragma unroll
    for (int l = 0; l < NL; l++) {
        float s, c;
        __sincosf(qv[l], &s, &c);

        const float* Rf = &sR[l * 9];
        const float* tf = &sT[l * 3];

        // J = Rf @ Raxis  (axis known at compile time: even links = z, odd = y)
        float J0, J1, J2, J3, J4, J5, J6, J7, J8;
        if ((l & 1) == 0) {
            // Raxis_z = [[c,-s,0],[s,c,0],[0,0,1]]
            J0 = fmaf(c, Rf[0],  s * Rf[1]);  J1 = fmaf(-s, Rf[0], c * Rf[1]);  J2 = Rf[2];
            J3 = fmaf(c, Rf[3],  s * Rf[4]);  J4 = fmaf(-s, Rf[3], c * Rf[4]);  J5 = Rf[5];
            J6 = fmaf(c, Rf[6],  s * Rf[7]);  J7 = fmaf(-s, Rf[6], c * Rf[7]);  J8 = Rf[8];
        } else {
            // Raxis_y = [[c,0,s],[0,1,0],[-s,0,c]]
            J0 = fmaf(c, Rf[0], -s * Rf[2]);  J1 = Rf[1];  J2 = fmaf(s, Rf[0], c * Rf[2]);
            J3 = fmaf(c, Rf[3], -s * Rf[5]);  J4 = Rf[4];  J5 = fmaf(s, Rf[3], c * Rf[5]);
            J6 = fmaf(c, Rf[6], -s * Rf[8]);  J7 = Rf[7];  J8 = fmaf(s, Rf[6], c * Rf[8]);
        }

        // t_new = Rp @ tf + tp   (uses OLD R)
        float nt0 = fmaf(R0, tf[0], fmaf(R1, tf[1], fmaf(R2, tf[2], t0)));
        float nt1 = fmaf(R3, tf[0], fmaf(R4, tf[1], fmaf(R5, tf[2], t1)));
        float nt2 = fmaf(R6, tf[0], fmaf(R7, tf[1], fmaf(R8, tf[2], t2)));

        // R_new = Rp @ J
        float N0 = fmaf(R0, J0, fmaf(R1, J3, R2 * J6));
        float N1 = fmaf(R0, J1, fmaf(R1, J4, R2 * J7));
        float N2 = fmaf(R0, J2, fmaf(R1, J5, R2 * J8));
        float N3 = fmaf(R3, J0, fmaf(R4, J3, R5 * J6));
        float N4 = fmaf(R3, J1, fmaf(R4, J4, R5 * J7));
        float N5 = fmaf(R3, J2, fmaf(R4, J5, R5 * J8));
        float N6 = fmaf(R6, J0, fmaf(R7, J3, R8 * J6));
        float N7 = fmaf(R6, J1, fmaf(R7, J4, R8 * J7));
        float N8 = fmaf(R6, J2, fmaf(R7, J5, R8 * J8));

        R0 = N0; R1 = N1; R2 = N2;
        R3 = N3; R4 = N4; R5 = N5;
        R6 = N6; R7 = N7; R8 = N8;
        t0 = nt0; t1 = nt1; t2 = nt2;

        // ---- write position ----
        size_t tbase = ((size_t)l * BATCH + b) * 3;
        ts_out[tbase + 0] = t0;
        ts_out[tbase + 1] = t1;
        ts_out[tbase + 2] = t2;

        // ---- quaternion (matches reference: 4 sqrts + sign selects) ----
        const float eps = 1e-9f;
        float qw = 0.5f * sqrtf(fmaxf(1.f + R0 + R4 + R8, eps));
        float qx = 0.5f * sqrtf(fmaxf(1.f + R0 - R4 - R8, eps));
        float qy = 0.5f * sqrtf(fmaxf(1.f - R0 + R4 - R8, eps));
        float qz = 0.5f * sqrtf(fmaxf(1.f - R0 - R4 + R8, eps));
        // sx = sign(R[2,1]-R[1,2]) = sign(R7 - R5), negative -> -1 else +1
        float sx = (R7 - R5 < 0.f) ? -1.f : 1.f;
        // sy = sign(R[0,2]-R[2,0]) = sign(R2 - R6)
        float sy = (R2 - R6 < 0.f) ? -1.f : 1.f;
        // sz = sign(R[1,0]-R[0,1]) = sign(R3 - R1)
        float sz = (R3 - R1 < 0.f) ? -1.f : 1.f;

        qu_out[(size_t)l * BATCH + b] = make_float4(sx * qx, sy * qy, sz * qz, qw);
    }
}

extern "C" void kernel_launch(void* const* d_in, const int* in_sizes, int n_in,
                              void* d_out, int out_size) {
    const float* q           = (const float*)d_in[0];
    const float* rot_fixed   = (const float*)d_in[1];
    const float* trans_fixed = (const float*)d_in[2];
    float* out = (float*)d_out;

    const int threads = 256;
    const int blocks = (BATCH + threads - 1) / threads;
    fk_kernel<<<blocks, threads>>>(q, rot_fixed, trans_fixed, out);
}